// round 1
// baseline (speedup 1.0000x reference)
#include <cuda_runtime.h>

// Problem constants (fixed by the reference)
#define BATCH   4096
#define FEAT    40960
#define ACCUM   512
#define H1      32
#define H2      32
#define MAXIDX  128   // cap on active features per row (mean ~30, Poisson tail safe)

// Scratch: transposed feature-transform weights, [FEAT][ACCUM]
__device__ float g_ftT[(size_t)FEAT * ACCUM];
// stm dtype mode: 0 = 1-byte bool, 1 = int32, 2 = float32
__device__ int g_stm_mode;

// ---------------------------------------------------------------------------
// Kernel 0: detect stm dtype from first 4096 bytes (safe to read under all
// three candidate dtypes since bool buffer is exactly 4096 bytes).
// int32 0/1 pattern: every 4-byte group is [v,0,0,0] with v<=1.
// float32 0.0/1.0 pattern: group is [0,0,0,0] or [0,0,0x80,0x3F].
// Otherwise: 1-byte bool.
// ---------------------------------------------------------------------------
__global__ void detect_stm_kernel(const unsigned char* __restrict__ stm) {
    __shared__ int bad_int, bad_f32;
    if (threadIdx.x == 0) { bad_int = 0; bad_f32 = 0; }
    __syncthreads();
    for (int g = threadIdx.x; g < 1024; g += blockDim.x) {
        unsigned char b0 = stm[4*g+0], b1 = stm[4*g+1];
        unsigned char b2 = stm[4*g+2], b3 = stm[4*g+3];
        if (!((b1 | b2 | b3) == 0 && b0 <= 1)) atomicOr(&bad_int, 1);
        bool zero = (b0 | b1 | b2 | b3) == 0;
        bool one  = (b0 == 0 && b1 == 0 && b2 == 0x80 && b3 == 0x3F);
        if (!(zero || one)) atomicOr(&bad_f32, 1);
    }
    __syncthreads();
    if (threadIdx.x == 0)
        g_stm_mode = (!bad_int) ? 1 : ((!bad_f32) ? 2 : 0);
}

// ---------------------------------------------------------------------------
// Kernel 1: transpose ft_w [ACCUM, FEAT] -> g_ftT [FEAT, ACCUM]
// Tiled 32x32 with padded shared to avoid bank conflicts. 84 MB each way.
// ---------------------------------------------------------------------------
__global__ void transpose_kernel(const float* __restrict__ ftw) {
    __shared__ float tile[32][33];
    int fx = blockIdx.x * 32;           // feature tile origin
    int oy = blockIdx.y * 32;           // output tile origin
    int tx = threadIdx.x, ty = threadIdx.y;   // block (32, 8)
    #pragma unroll
    for (int j = 0; j < 32; j += 8)
        tile[ty + j][tx] = ftw[(size_t)(oy + ty + j) * FEAT + (fx + tx)];
    __syncthreads();
    #pragma unroll
    for (int j = 0; j < 32; j += 8)
        g_ftT[(size_t)(fx + ty + j) * ACCUM + (oy + tx)] = tile[tx][ty + j];
}

// ---------------------------------------------------------------------------
// Kernel 2: full NNUE forward, one block per batch row, 512 threads.
// Phase A: stream the two 160KB feature rows (float4), collect active indices.
// Phase B: register-accumulate ACCUM outputs from g_ftT columns (L2 hits).
// Phase C: screlu + stm-select -> shared x[1024]; L1 (16 warps x 2 outputs),
//          L2 layer + output head in warp 0.
// ---------------------------------------------------------------------------
__global__ __launch_bounds__(512, 2) void nnue_kernel(
    const float* __restrict__ wf, const float* __restrict__ bf,
    const unsigned char* __restrict__ stm_raw,
    const float* __restrict__ ft_b,
    const float* __restrict__ l1_w, const float* __restrict__ l1_b,
    const float* __restrict__ l2_w, const float* __restrict__ l2_b,
    const float* __restrict__ out_w, const float* __restrict__ out_b,
    float* __restrict__ out)
{
    const int row = blockIdx.x;
    const int t   = threadIdx.x;

    __shared__ int   idxw[MAXIDX], idxb[MAXIDX];
    __shared__ int   nw, nb;
    __shared__ float x[2 * ACCUM];
    __shared__ float v1[H1];

    if (t == 0) { nw = 0; nb = 0; }
    __syncthreads();

    // ---- Phase A: scan features (vectorized), gather active indices ----
    const float4* wrow = (const float4*)(wf + (size_t)row * FEAT);
    const float4* brow = (const float4*)(bf + (size_t)row * FEAT);
    #pragma unroll
    for (int i = 0; i < FEAT / 4 / 512; i++) {   // 20 iterations
        int vi = t + i * 512;
        float4 v = wrow[vi];
        if (v.x != 0.f) { int p = atomicAdd(&nw, 1); if (p < MAXIDX) idxw[p] = 4*vi + 0; }
        if (v.y != 0.f) { int p = atomicAdd(&nw, 1); if (p < MAXIDX) idxw[p] = 4*vi + 1; }
        if (v.z != 0.f) { int p = atomicAdd(&nw, 1); if (p < MAXIDX) idxw[p] = 4*vi + 2; }
        if (v.w != 0.f) { int p = atomicAdd(&nw, 1); if (p < MAXIDX) idxw[p] = 4*vi + 3; }
        float4 u = brow[vi];
        if (u.x != 0.f) { int p = atomicAdd(&nb, 1); if (p < MAXIDX) idxb[p] = 4*vi + 0; }
        if (u.y != 0.f) { int p = atomicAdd(&nb, 1); if (p < MAXIDX) idxb[p] = 4*vi + 1; }
        if (u.z != 0.f) { int p = atomicAdd(&nb, 1); if (p < MAXIDX) idxb[p] = 4*vi + 2; }
        if (u.w != 0.f) { int p = atomicAdd(&nb, 1); if (p < MAXIDX) idxb[p] = 4*vi + 3; }
    }
    __syncthreads();

    const int cw = min(nw, MAXIDX), cb = min(nb, MAXIDX);

    // ---- Phase B: accumulate (4-way MLP for L2-latency hiding) ----
    float a0 = 0.f, a1 = 0.f, a2 = 0.f, a3 = 0.f;
    int k = 0;
    for (; k + 4 <= cw; k += 4) {
        a0 += g_ftT[(size_t)idxw[k+0] * ACCUM + t];
        a1 += g_ftT[(size_t)idxw[k+1] * ACCUM + t];
        a2 += g_ftT[(size_t)idxw[k+2] * ACCUM + t];
        a3 += g_ftT[(size_t)idxw[k+3] * ACCUM + t];
    }
    for (; k < cw; k++) a0 += g_ftT[(size_t)idxw[k] * ACCUM + t];
    float accw = ft_b[t] + (a0 + a1) + (a2 + a3);

    float b0 = 0.f, b1 = 0.f, b2 = 0.f, b3 = 0.f;
    k = 0;
    for (; k + 4 <= cb; k += 4) {
        b0 += g_ftT[(size_t)idxb[k+0] * ACCUM + t];
        b1 += g_ftT[(size_t)idxb[k+1] * ACCUM + t];
        b2 += g_ftT[(size_t)idxb[k+2] * ACCUM + t];
        b3 += g_ftT[(size_t)idxb[k+3] * ACCUM + t];
    }
    for (; k < cb; k++) b0 += g_ftT[(size_t)idxb[k] * ACCUM + t];
    float accb = ft_b[t] + (b0 + b1) + (b2 + b3);

    // screlu
    accw = fminf(fmaxf(accw, 0.f), 1.f); accw *= accw;
    accb = fminf(fmaxf(accb, 0.f), 1.f); accb *= accb;

    // stm select (dtype-mode decoded)
    bool s;
    {
        int mode = g_stm_mode;
        if (mode == 1)      s = ((const int*)stm_raw)[row] != 0;
        else if (mode == 2) s = ((const float*)stm_raw)[row] != 0.f;
        else                s = stm_raw[row] != 0;
    }
    x[t]         = s ? accb : accw;
    x[ACCUM + t] = s ? accw : accb;
    __syncthreads();

    // ---- Phase C: L1 (32 outputs x 1024 dot), 16 warps x 2 outputs ----
    const int warp = t >> 5, lane = t & 31;
    #pragma unroll
    for (int oo = 0; oo < 2; oo++) {
        int o = warp * 2 + oo;
        const float* w1 = l1_w + (size_t)o * (2 * ACCUM);
        float sum = 0.f;
        #pragma unroll
        for (int j = lane; j < 2 * ACCUM; j += 32)
            sum += x[j] * w1[j];
        #pragma unroll
        for (int off = 16; off > 0; off >>= 1)
            sum += __shfl_down_sync(0xffffffffu, sum, off);
        if (lane == 0) {
            sum += l1_b[o];
            sum = fminf(fmaxf(sum, 0.f), 1.f);
            v1[o] = sum * sum;
        }
    }
    __syncthreads();

    // ---- L2 layer (32x32) + output head in warp 0 ----
    if (warp == 0) {
        float sum = l2_b[lane];
        #pragma unroll
        for (int j = 0; j < H1; j++)
            sum += v1[j] * l2_w[lane * H1 + j];
        sum = fminf(fmaxf(sum, 0.f), 1.f);
        float vv = sum * sum * out_w[lane];
        #pragma unroll
        for (int off = 16; off > 0; off >>= 1)
            vv += __shfl_down_sync(0xffffffffu, vv, off);
        if (lane == 0) out[row] = vv + out_b[0];
    }
}

// ---------------------------------------------------------------------------
// Input order (metadata): white_features, black_features, stm, ft_w, ft_b,
//                         l1_w, l1_b, l2_w, l2_b, out_w, out_b
// ---------------------------------------------------------------------------
extern "C" void kernel_launch(void* const* d_in, const int* in_sizes, int n_in,
                              void* d_out, int out_size) {
    const float*         wf    = (const float*)d_in[0];
    const float*         bf    = (const float*)d_in[1];
    const unsigned char* stm   = (const unsigned char*)d_in[2];
    const float*         ft_w  = (const float*)d_in[3];
    const float*         ft_b  = (const float*)d_in[4];
    const float*         l1_w  = (const float*)d_in[5];
    const float*         l1_b  = (const float*)d_in[6];
    const float*         l2_w  = (const float*)d_in[7];
    const float*         l2_b  = (const float*)d_in[8];
    const float*         out_w = (const float*)d_in[9];
    const float*         out_b = (const float*)d_in[10];
    float*               out   = (float*)d_out;

    detect_stm_kernel<<<1, 256>>>(stm);

    dim3 tgrid(FEAT / 32, ACCUM / 32);
    dim3 tblock(32, 8);
    transpose_kernel<<<tgrid, tblock>>>(ft_w);

    nnue_kernel<<<BATCH, 512>>>(wf, bf, stm, ft_b, l1_w, l1_b,
                                l2_w, l2_b, out_w, out_b, out);
}